// round 1
// baseline (speedup 1.0000x reference)
#include <cuda_runtime.h>
#include <cuda_bf16.h>

// RoPE3DEncoder: T=32, H=64, W=64, DIM=192 (DIM_X=DIM_Y=DIM_T=64).
// All three inv_freq tables are identical (d=64 each), so a single
// 64-position x 64-col (duplicated halves) cos/sin table covers every axis:
//   table[pos][c] = cos/sin(pos * 10000^(-2*(c%32)/64))
// Row layout: [x-cols(64) | y-cols(64) | t-cols(64)], row = t*4096 + h*64 + w.
// Output: cos table [131072*192] floats followed by sin table.

#define ROWS   131072              // 32*64*64
#define QPR    48                  // float4 quads per 192-float row
#define NQ     (ROWS * QPR)        // 6,291,456 quads per table

__device__ __align__(16) float g_cos[64 * 64];
__device__ __align__(16) float g_sin[64 * 64];

__global__ void rope_precompute_tables() {
    int tid = blockIdx.x * blockDim.x + threadIdx.x;
    if (tid >= 64 * 32) return;
    int pos = tid >> 5;
    int j   = tid & 31;
    // inv_freq[j] = 1 / 10000^{(2j)/64}
    float invf = powf(10000.0f, -(float)(2 * j) / 64.0f);
    float ang  = (float)pos * invf;
    float s, c;
    sincosf(ang, &s, &c);   // accurate sincos; only 2048 of these, cost ~0
    g_cos[pos * 64 + j]      = c;
    g_cos[pos * 64 + j + 32] = c;   // duplicated second half
    g_sin[pos * 64 + j]      = s;
    g_sin[pos * 64 + j + 32] = s;
}

__global__ void __launch_bounds__(256) rope_broadcast(float4* __restrict__ out) {
    unsigned idx = blockIdx.x * blockDim.x + threadIdx.x;   // quad index
    unsigned row = idx / 48u;
    unsigned q   = idx - row * 48u;
    unsigned c4  = q * 4u;                 // starting column of this quad

    unsigned w = row & 63u;
    unsigned h = (row >> 6) & 63u;
    unsigned t = row >> 12;

    // Which axis does this quad belong to? (quads never straddle 64/128)
    unsigned pos = (c4 < 64u) ? w : ((c4 < 128u) ? h : t);
    unsigned off = pos * 64u + (c4 & 63u);

    float4 vc = *reinterpret_cast<const float4*>(g_cos + off);
    float4 vs = *reinterpret_cast<const float4*>(g_sin + off);

    out[idx]      = vc;   // cos half of output
    out[NQ + idx] = vs;   // sin half of output
}

extern "C" void kernel_launch(void* const* d_in, const int* in_sizes, int n_in,
                              void* d_out, int out_size) {
    (void)d_in; (void)in_sizes; (void)n_in; (void)out_size;
    // 2048 table entries, 8 blocks of 256
    rope_precompute_tables<<<8, 256>>>();
    // 6,291,456 quads / 256 = 24576 blocks, exact
    rope_broadcast<<<NQ / 256, 256>>>(reinterpret_cast<float4*>(d_out));
}